// round 1
// baseline (speedup 1.0000x reference)
#include <cuda_runtime.h>

// ---------------------------------------------------------------------------
// MyModel_87522843559014: LSTM(B=256,T=512,F=128,H=256) + MLP head
// Pipeline (4 kernels in one graph):
//   0) reset_kernel   : zero grid-barrier state (replay-deterministic)
//   1) xz_gemm_kernel : xz[t*256+b][col] = x[b,t,:] @ kernel[:,col]   (512MB scratch)
//   2) lstm_kernel    : 128 persistent blocks, 512 steps, software grid barrier
//   3) head_kernel    : relu(h @ w1 + b1) @ w2 + b2
// ---------------------------------------------------------------------------

#define LSTM_GRID 128
#define SW 260   // smem row stride (floats): 260 = 65 float4 (odd) -> conflict-free

__device__ float g_xz[512u * 256u * 1024u];   // [T][B][4H] fp32, 512 MB scratch
__device__ float g_h[2][256][256];            // double-buffered hidden state
__device__ unsigned g_bar;
__device__ volatile unsigned g_flag;

__global__ void reset_kernel() { g_bar = 0u; g_flag = 0u; }

// ---------------- software grid barrier (all 128 blocks co-resident) --------
__device__ __forceinline__ void grid_barrier(unsigned id) {
    __threadfence();               // publish this thread's global writes (gpu scope)
    __syncthreads();
    if (threadIdx.x == 0) {
        unsigned prev = atomicAdd(&g_bar, 1u);
        if (prev == id * LSTM_GRID - 1u) {
            g_flag = id;           // volatile store (release point)
        }
        while (g_flag < id) { }    // volatile spin (bypasses L1)
        __threadfence();           // acquire: order subsequent reads
    }
    __syncthreads();
}

// ---------------- input projection GEMM -------------------------------------
// Block tile 128(m) x 128(n), 256 threads, 8x8 per thread, K chunk 8, K=128.
__global__ void __launch_bounds__(256, 2)
xz_gemm_kernel(const float* __restrict__ x, const float* __restrict__ kern) {
    __shared__ float As[8][132];
    __shared__ float Bs[8][132];

    const int tid = threadIdx.x;
    const int nb = blockIdx.x;          // 0..7
    const int mb = blockIdx.y;          // 0..1023
    const int m0 = mb * 128, n0 = nb * 128;

    // A load mapping: each thread fetches one float4 (4 k's of one row)
    const int lrow = tid >> 1;          // 0..127
    const int lk4  = (tid & 1) * 4;     // 0 or 4
    const int m    = m0 + lrow;
    const int tt   = m >> 8;            // t
    const int bb   = m & 255;           // b
    const float* xrow = x + ((size_t)bb * 512 + tt) * 128;

    // B load mapping
    const int bk = tid >> 5;            // 0..7
    const int bn = (tid & 31) * 4;      // 0..124

    const int tm = (tid >> 4) * 8;
    const int tn = (tid & 15) * 8;

    float acc[8][8];
#pragma unroll
    for (int i = 0; i < 8; i++)
#pragma unroll
        for (int j = 0; j < 8; j++) acc[i][j] = 0.f;

    for (int k0 = 0; k0 < 128; k0 += 8) {
        float4 av = *(const float4*)(xrow + k0 + lk4);
        float4 bv = *(const float4*)(kern + (size_t)(k0 + bk) * 1024 + n0 + bn);
        __syncthreads();   // previous iter's smem reads done
        As[lk4 + 0][lrow] = av.x;
        As[lk4 + 1][lrow] = av.y;
        As[lk4 + 2][lrow] = av.z;
        As[lk4 + 3][lrow] = av.w;
        *(float4*)&Bs[bk][bn] = bv;
        __syncthreads();
#pragma unroll
        for (int kk = 0; kk < 8; kk++) {
            float4 a0 = *(const float4*)&As[kk][tm];
            float4 a1 = *(const float4*)&As[kk][tm + 4];
            float4 b0 = *(const float4*)&Bs[kk][tn];
            float4 b1 = *(const float4*)&Bs[kk][tn + 4];
            float ar[8] = {a0.x, a0.y, a0.z, a0.w, a1.x, a1.y, a1.z, a1.w};
            float br[8] = {b0.x, b0.y, b0.z, b0.w, b1.x, b1.y, b1.z, b1.w};
#pragma unroll
            for (int i = 0; i < 8; i++)
#pragma unroll
                for (int j = 0; j < 8; j++)
                    acc[i][j] = fmaf(ar[i], br[j], acc[i][j]);
        }
    }

#pragma unroll
    for (int i = 0; i < 8; i++) {
        float* dst = g_xz + (size_t)(m0 + tm + i) * 1024 + n0 + tn;
        *(float4*)(dst + 0) = make_float4(acc[i][0], acc[i][1], acc[i][2], acc[i][3]);
        *(float4*)(dst + 4) = make_float4(acc[i][4], acc[i][5], acc[i][6], acc[i][7]);
    }
}

// ---------------- fast activations -------------------------------------------
__device__ __forceinline__ float sigf(float x)  { return 1.f / (1.f + __expf(-x)); }
__device__ __forceinline__ float tanhfast(float x) { return 2.f / (1.f + __expf(-2.f * x)) - 1.f; }

// ---------------- persistent LSTM kernel -------------------------------------
// 128 blocks: blockIdx = bt*16 + jt; each owns 32 batches x 16 hidden units.
// Per step: z[b, g*256+j] = xz[t][b][col] + h[b,:] . rkernel[:,col]  (64 cols/block)
__global__ void __launch_bounds__(256, 1)
lstm_kernel(const float* __restrict__ rkernel) {
    extern __shared__ float smem[];
    float* w_s = smem;                  // [64][SW]  rkernel tile (resident all steps)
    float* h_s = w_s + 64 * SW;         // [32][SW]  h tile (reloaded per step)
    float* zs  = h_s + 32 * SW;         // [64][33]  gate pre-activation staging
    float* c_s = zs + 64 * 33;          // [512]     cell state (persistent)

    const int tid = threadIdx.x;
    const int bt = blockIdx.x >> 4;     // 0..7
    const int jt = blockIdx.x & 15;     // 0..15
    const int bbase = bt * 32, jbase = jt * 16;

    // init: c=0, and zero our slice of h_buf[0]
    for (int p = tid; p < 512; p += 256) {
        int bb = p >> 4, jj = p & 15;
        c_s[p] = 0.f;
        g_h[0][bbase + bb][jbase + jj] = 0.f;
    }
    // load rkernel tile transposed: w_s[c][k] = rkernel[k][G(c)]
    for (int idx = tid; idx < 64 * 256; idx += 256) {
        int c = idx & 63, k = idx >> 6;
        int col = (c >> 4) * 256 + jbase + (c & 15);
        w_s[c * SW + k] = rkernel[k * 1024 + col];
    }
    grid_barrier(1);

    const int wid = tid >> 5, lane = tid & 31;
    const int b0 = (wid >> 1) * 8;               // batch sub-tile base (0,8,16,24)
    const int c  = (wid & 1) * 32 + lane;        // local gate col 0..63
    const int col = (c >> 4) * 256 + jbase + (c & 15);
    const float* wp = &w_s[c * SW];

    for (int t = 0; t < 512; t++) {
        const int par = t & 1;
        // load h tile [32][256] from L2 (MUST bypass L1: cross-SM producer)
        const float4* hsrc = (const float4*)&g_h[par][bbase][0];
        for (int i = tid; i < 32 * 64; i += 256) {
            float4 v = __ldcg(hsrc + i);
            int r = i >> 6, q = i & 63;
            *(float4*)&h_s[r * SW + q * 4] = v;
        }
        __syncthreads();

        float acc[8] = {0.f, 0.f, 0.f, 0.f, 0.f, 0.f, 0.f, 0.f};
#pragma unroll 4
        for (int kk = 0; kk < 64; kk++) {
            float4 wv = *(const float4*)(wp + kk * 4);
#pragma unroll
            for (int r = 0; r < 8; r++) {
                float4 hv = *(const float4*)&h_s[(b0 + r) * SW + kk * 4];
                acc[r] = fmaf(hv.x, wv.x, acc[r]);
                acc[r] = fmaf(hv.y, wv.y, acc[r]);
                acc[r] = fmaf(hv.z, wv.z, acc[r]);
                acc[r] = fmaf(hv.w, wv.w, acc[r]);
            }
        }
        const float* xzrow = &g_xz[((size_t)(t * 256 + bbase + b0)) * 1024 + col];
#pragma unroll
        for (int r = 0; r < 8; r++) {
            float z = acc[r] + __ldcg(xzrow + (size_t)r * 1024);
            zs[c * 33 + b0 + r] = z;
        }
        __syncthreads();

        // elementwise gates: 512 (b,j) pairs, 2 per thread
#pragma unroll
        for (int pp = 0; pp < 2; pp++) {
            int p = tid + pp * 256;
            int bb = p >> 4, jj = p & 15;
            float zi = zs[jj * 33 + bb];
            float zf = zs[(16 + jj) * 33 + bb];
            float zg = zs[(32 + jj) * 33 + bb];
            float zo = zs[(48 + jj) * 33 + bb];
            float cn = sigf(zf) * c_s[p] + sigf(zi) * tanhfast(zg);
            c_s[p] = cn;
            g_h[par ^ 1][bbase + bb][jbase + jj] = sigf(zo) * tanhfast(cn);
        }
        if (t < 511) grid_barrier((unsigned)(t + 2));
    }
    // final h is in g_h[0] (512 is even); kernel boundary syncs before head
}

// ---------------- MLP head ---------------------------------------------------
__global__ void __launch_bounds__(256)
head_kernel(const float* __restrict__ w1, const float* __restrict__ b1,
            const float* __restrict__ w2, const float* __restrict__ b2,
            float* __restrict__ out) {
    __shared__ float hs[256];
    __shared__ float ys[100];
    const int b = blockIdx.x, tid = threadIdx.x;
    hs[tid] = g_h[0][b][tid];
    __syncthreads();
    if (tid < 100) {
        float a = b1[tid];
#pragma unroll 4
        for (int k = 0; k < 256; k++) a = fmaf(hs[k], w1[k * 100 + tid], a);
        ys[tid] = fmaxf(a, 0.f);
    }
    __syncthreads();
    if (tid == 0) {
        float s = b2[0];
        for (int j = 0; j < 100; j++) s = fmaf(ys[j], w2[j], s);
        out[b] = s;
    }
}

// ---------------- launch ------------------------------------------------------
extern "C" void kernel_launch(void* const* d_in, const int* in_sizes, int n_in,
                              void* d_out, int out_size) {
    const float* x    = (const float*)d_in[0];
    const float* kern = (const float*)d_in[1];
    const float* rk   = (const float*)d_in[2];
    const float* w1   = (const float*)d_in[3];
    const float* b1   = (const float*)d_in[4];
    const float* w2   = (const float*)d_in[5];
    const float* b2   = (const float*)d_in[6];
    float* out = (float*)d_out;

    const int smem_bytes = (64 * SW + 32 * SW + 64 * 33 + 512) * 4;  // 110336
    cudaFuncSetAttribute(lstm_kernel, cudaFuncAttributeMaxDynamicSharedMemorySize,
                         smem_bytes);

    reset_kernel<<<1, 1>>>();
    dim3 gg(8, 1024);
    xz_gemm_kernel<<<gg, 256>>>(x, kern);
    lstm_kernel<<<LSTM_GRID, 256, smem_bytes>>>(rk);
    head_kernel<<<256, 256>>>(w1, b1, w2, b2, out);
}

// round 2
// speedup vs baseline: 1.0884x; 1.0884x over previous
#include <cuda_runtime.h>

// ---------------------------------------------------------------------------
// MyModel_87522843559014: LSTM(B=256,T=512,F=128,H=256) + MLP head
//   0) reset_kernel   : zero barrier counters (replay-deterministic)
//   1) xz_gemm_kernel : xz = x @ kernel, f32x2 packed FMA
//   2) lstm_kernel    : 128 persistent blocks, 8 independent 16-block groups,
//                       f32x2 packed inner product, per-group barriers
//   3) head_kernel    : relu(h @ w1 + b1) @ w2 + b2
// ---------------------------------------------------------------------------

#define LSTM_GRID 128
#define SW 260   // smem row stride (floats): odd multiple of 4 -> conflict-free

typedef unsigned long long ull;

__device__ float g_xz[512u * 256u * 1024u];   // [T][B][4H] fp32
__device__ float g_h[2][256][256];            // double-buffered hidden state
__device__ unsigned g_cnt[8];                 // per-batch-group arrival counters

__global__ void reset_kernel() {
    if (threadIdx.x < 8) g_cnt[threadIdx.x] = 0u;
}

// ---------------- f32x2 helpers ----------------------------------------------
__device__ __forceinline__ ull fma2(ull a, ull b, ull c) {
    ull d;
    asm("fma.rn.f32x2 %0, %1, %2, %3;" : "=l"(d) : "l"(a), "l"(b), "l"(c));
    return d;
}
__device__ __forceinline__ ull dup2(float x) {
    ull r;
    asm("mov.b64 %0, {%1, %1};" : "=l"(r) : "f"(x));
    return r;
}
__device__ __forceinline__ float lo32(ull v) { return __uint_as_float((unsigned)v); }
__device__ __forceinline__ float hi32(ull v) { return __uint_as_float((unsigned)(v >> 32)); }

// ---------------- per-group barrier (16 blocks share one counter) ------------
__device__ __forceinline__ void group_wait(int bt, unsigned target) {
    __threadfence();               // release all prior global writes
    __syncthreads();
    if (threadIdx.x == 0) {
        atomicAdd(&g_cnt[bt], 1u);
        unsigned v;
        do {
            asm volatile("ld.global.acquire.gpu.u32 %0, [%1];"
                         : "=r"(v) : "l"(&g_cnt[bt]) : "memory");
        } while (v < target);
    }
    __syncthreads();
}

// ---------------- input projection GEMM (f32x2) -------------------------------
// Block tile 128(m) x 128(n), 256 threads, thread tile 8x8 (4 m-pairs x 8 n).
__global__ void __launch_bounds__(256, 2)
xz_gemm_kernel(const float* __restrict__ x, const float* __restrict__ kern) {
    __shared__ float As[8][132];
    __shared__ float Bs[8][132];

    const int tid = threadIdx.x;
    const int nb = blockIdx.x;          // 0..7
    const int mb = blockIdx.y;          // 0..1023
    const int m0 = mb * 128, n0 = nb * 128;

    const int lrow = tid >> 1;
    const int lk4  = (tid & 1) * 4;
    const int m    = m0 + lrow;
    const int tt   = m >> 8;
    const int bb   = m & 255;
    const float* xrow = x + ((size_t)bb * 512 + tt) * 128;

    const int bk = tid >> 5;
    const int bn = (tid & 31) * 4;

    const int tm = (tid >> 4) * 8;
    const int tn = (tid & 15) * 8;

    ull acc2[4][8];
#pragma unroll
    for (int i = 0; i < 4; i++)
#pragma unroll
        for (int j = 0; j < 8; j++) acc2[i][j] = 0ull;

    for (int k0 = 0; k0 < 128; k0 += 8) {
        float4 av = *(const float4*)(xrow + k0 + lk4);
        float4 bv = *(const float4*)(kern + (size_t)(k0 + bk) * 1024 + n0 + bn);
        __syncthreads();
        As[lk4 + 0][lrow] = av.x;
        As[lk4 + 1][lrow] = av.y;
        As[lk4 + 2][lrow] = av.z;
        As[lk4 + 3][lrow] = av.w;
        *(float4*)&Bs[bk][bn] = bv;
        __syncthreads();
#pragma unroll
        for (int kk = 0; kk < 8; kk++) {
            ulonglong2 a0 = *(const ulonglong2*)&As[kk][tm];       // m pairs (0,1),(2,3)
            ulonglong2 a1 = *(const ulonglong2*)&As[kk][tm + 4];   // m pairs (4,5),(6,7)
            ull ap[4] = {a0.x, a0.y, a1.x, a1.y};
            float4 b0 = *(const float4*)&Bs[kk][tn];
            float4 b1 = *(const float4*)&Bs[kk][tn + 4];
            {
                ull bd0 = dup2(b0.x), bd1 = dup2(b0.y), bd2 = dup2(b0.z), bd3 = dup2(b0.w);
#pragma unroll
                for (int i = 0; i < 4; i++) {
                    acc2[i][0] = fma2(ap[i], bd0, acc2[i][0]);
                    acc2[i][1] = fma2(ap[i], bd1, acc2[i][1]);
                    acc2[i][2] = fma2(ap[i], bd2, acc2[i][2]);
                    acc2[i][3] = fma2(ap[i], bd3, acc2[i][3]);
                }
            }
            {
                ull bd4 = dup2(b1.x), bd5 = dup2(b1.y), bd6 = dup2(b1.z), bd7 = dup2(b1.w);
#pragma unroll
                for (int i = 0; i < 4; i++) {
                    acc2[i][4] = fma2(ap[i], bd4, acc2[i][4]);
                    acc2[i][5] = fma2(ap[i], bd5, acc2[i][5]);
                    acc2[i][6] = fma2(ap[i], bd6, acc2[i][6]);
                    acc2[i][7] = fma2(ap[i], bd7, acc2[i][7]);
                }
            }
        }
    }

    // store: acc2[i2][j] holds rows (tm+2*i2, tm+2*i2+1), col tn+j
#pragma unroll
    for (int i2 = 0; i2 < 4; i2++) {
        float* d0 = g_xz + (size_t)(m0 + tm + 2 * i2) * 1024 + n0 + tn;
        float* d1 = d0 + 1024;
        *(float4*)(d0 + 0) = make_float4(lo32(acc2[i2][0]), lo32(acc2[i2][1]),
                                         lo32(acc2[i2][2]), lo32(acc2[i2][3]));
        *(float4*)(d0 + 4) = make_float4(lo32(acc2[i2][4]), lo32(acc2[i2][5]),
                                         lo32(acc2[i2][6]), lo32(acc2[i2][7]));
        *(float4*)(d1 + 0) = make_float4(hi32(acc2[i2][0]), hi32(acc2[i2][1]),
                                         hi32(acc2[i2][2]), hi32(acc2[i2][3]));
        *(float4*)(d1 + 4) = make_float4(hi32(acc2[i2][4]), hi32(acc2[i2][5]),
                                         hi32(acc2[i2][6]), hi32(acc2[i2][7]));
    }
}

// ---------------- fast activations -------------------------------------------
__device__ __forceinline__ float sigf(float x)     { return 1.f / (1.f + __expf(-x)); }
__device__ __forceinline__ float tanhfast(float x) { return 2.f / (1.f + __expf(-2.f * x)) - 1.f; }

// ---------------- persistent LSTM kernel -------------------------------------
// blockIdx = bt*16 + jt. Groups of 16 blocks (same bt) sync among themselves.
__global__ void __launch_bounds__(256, 1)
lstm_kernel(const float* __restrict__ rkernel) {
    extern __shared__ float smem[];
    float* w_s = smem;                  // [64][SW]  rkernel tile (resident)
    float* h_s = w_s + 64 * SW;         // [32][SW]  h tile
    float* zs  = h_s + 32 * SW;         // [64][33]  gate staging
    float* c_s = zs + 64 * 33;          // [512]     cell state

    const int tid = threadIdx.x;
    const int bt = blockIdx.x >> 4;     // 0..7 (batch group)
    const int jt = blockIdx.x & 15;     // 0..15
    const int bbase = bt * 32, jbase = jt * 16;

    for (int p = tid; p < 512; p += 256) {
        int bb = p >> 4, jj = p & 15;
        c_s[p] = 0.f;
        g_h[0][bbase + bb][jbase + jj] = 0.f;
    }
    for (int idx = tid; idx < 64 * 256; idx += 256) {
        int c = idx & 63, k = idx >> 6;
        int col = (c >> 4) * 256 + jbase + (c & 15);
        w_s[c * SW + k] = rkernel[k * 1024 + col];
    }
    group_wait(bt, 16u);   // all 16 group blocks wrote their h0 slice

    const int wid = tid >> 5, lane = tid & 31;
    const int b0 = (wid >> 1) * 8;               // batch sub-tile base
    const int c  = (wid & 1) * 32 + lane;        // local gate col 0..63
    const int col = (c >> 4) * 256 + jbase + (c & 15);
    const float* wp = &w_s[c * SW];

    for (int t = 0; t < 512; t++) {
        const int par = t & 1;
        // h tile from L2 (cross-SM producer -> must bypass L1)
        const float4* hsrc = (const float4*)&g_h[par][bbase][0];
        for (int i = tid; i < 32 * 64; i += 256) {
            float4 v = __ldcg(hsrc + i);
            int r = i >> 6, q = i & 63;
            *(float4*)&h_s[r * SW + q * 4] = v;
        }
        __syncthreads();

        ull acc2[8];
#pragma unroll
        for (int r = 0; r < 8; r++) acc2[r] = 0ull;
#pragma unroll 4
        for (int kk = 0; kk < 64; kk++) {
            ulonglong2 wv = *(const ulonglong2*)(wp + kk * 4);
#pragma unroll
            for (int r = 0; r < 8; r++) {
                ulonglong2 hv = *(const ulonglong2*)&h_s[(b0 + r) * SW + kk * 4];
                acc2[r] = fma2(hv.x, wv.x, acc2[r]);
                acc2[r] = fma2(hv.y, wv.y, acc2[r]);
            }
        }
        const float* xzrow = &g_xz[((size_t)(t * 256 + bbase + b0)) * 1024 + col];
#pragma unroll
        for (int r = 0; r < 8; r++) {
            float z = lo32(acc2[r]) + hi32(acc2[r]) + __ldcg(xzrow + (size_t)r * 1024);
            zs[c * 33 + b0 + r] = z;
        }
        __syncthreads();

        // elementwise gates: 512 (b,j) pairs, 2 per thread
#pragma unroll
        for (int pp = 0; pp < 2; pp++) {
            int p = tid + pp * 256;
            int bb = p >> 4, jj = p & 15;
            float zi = zs[jj * 33 + bb];
            float zf = zs[(16 + jj) * 33 + bb];
            float zg = zs[(32 + jj) * 33 + bb];
            float zo = zs[(48 + jj) * 33 + bb];
            float cn = sigf(zf) * c_s[p] + sigf(zi) * tanhfast(zg);
            c_s[p] = cn;
            g_h[par ^ 1][bbase + bb][jbase + jj] = sigf(zo) * tanhfast(cn);
        }
        if (t < 511) group_wait(bt, 16u * (unsigned)(t + 2));
    }
    // final h in g_h[0]; kernel boundary syncs before head
}

// ---------------- MLP head ---------------------------------------------------
__global__ void __launch_bounds__(256)
head_kernel(const float* __restrict__ w1, const float* __restrict__ b1,
            const float* __restrict__ w2, const float* __restrict__ b2,
            float* __restrict__ out) {
    __shared__ float hs[256];
    __shared__ float ys[100];
    const int b = blockIdx.x, tid = threadIdx.x;
    hs[tid] = g_h[0][b][tid];
    __syncthreads();
    if (tid < 100) {
        float a = b1[tid];
#pragma unroll 4
        for (int k = 0; k < 256; k++) a = fmaf(hs[k], w1[k * 100 + tid], a);
        ys[tid] = fmaxf(a, 0.f);
    }
    __syncthreads();
    if (tid == 0) {
        float s = b2[0];
        for (int j = 0; j < 100; j++) s = fmaf(ys[j], w2[j], s);
        out[b] = s;
    }
}

// ---------------- launch ------------------------------------------------------
extern "C" void kernel_launch(void* const* d_in, const int* in_sizes, int n_in,
                              void* d_out, int out_size) {
    const float* x    = (const float*)d_in[0];
    const float* kern = (const float*)d_in[1];
    const float* rk   = (const float*)d_in[2];
    const float* w1   = (const float*)d_in[3];
    const float* b1   = (const float*)d_in[4];
    const float* w2   = (const float*)d_in[5];
    const float* b2   = (const float*)d_in[6];
    float* out = (float*)d_out;

    const int smem_bytes = (64 * SW + 32 * SW + 64 * 33 + 512) * 4;  // 110336
    cudaFuncSetAttribute(lstm_kernel, cudaFuncAttributeMaxDynamicSharedMemorySize,
                         smem_bytes);

    reset_kernel<<<1, 8>>>();
    dim3 gg(8, 1024);
    xz_gemm_kernel<<<gg, 256>>>(x, kern);
    lstm_kernel<<<LSTM_GRID, 256, smem_bytes>>>(rk);
    head_kernel<<<256, 256>>>(w1, b1, w2, b2, out);
}

// round 3
// speedup vs baseline: 1.3107x; 1.2042x over previous
#include <cuda_runtime.h>

// ---------------------------------------------------------------------------
// MyModel_87522843559014: LSTM(B=256,T=512,F=128,H=256) + MLP head
//   0) reset_kernel   : zero barrier counters (replay-deterministic)
//   1) xz_gemm_kernel : xz = x @ kernel, f32x2 packed FMA
//   2) lstm_kernel    : 128 persistent blocks, 8 groups of 16, k-split warps,
//                       f32x2 inner product, xz prefetch, per-group barriers
//   3) head_kernel    : relu(h @ w1 + b1) @ w2 + b2
//   4) noop_kernel    : shifts ncu's fixed capture index onto lstm_kernel
// ---------------------------------------------------------------------------

#define LSTM_GRID 128
#define SW 260   // smem row stride (floats): odd multiple of 4 -> conflict-free

typedef unsigned long long ull;

__device__ float g_xz[512u * 256u * 1024u];   // [T][B][4H] fp32
__device__ float g_h[2][256][256];            // double-buffered hidden state
__device__ unsigned g_cnt[8];                 // per-batch-group arrival counters

__global__ void reset_kernel() {
    if (threadIdx.x < 8) g_cnt[threadIdx.x] = 0u;
}
__global__ void noop_kernel() {}

// ---------------- f32x2 helpers ----------------------------------------------
__device__ __forceinline__ ull fma2(ull a, ull b, ull c) {
    ull d;
    asm("fma.rn.f32x2 %0, %1, %2, %3;" : "=l"(d) : "l"(a), "l"(b), "l"(c));
    return d;
}
__device__ __forceinline__ ull dup2(float x) {
    ull r;
    asm("mov.b64 %0, {%1, %1};" : "=l"(r) : "f"(x));
    return r;
}
__device__ __forceinline__ float lo32(ull v) { return __uint_as_float((unsigned)v); }
__device__ __forceinline__ float hi32(ull v) { return __uint_as_float((unsigned)(v >> 32)); }

// ---------------- per-group barrier (16 blocks share one counter) ------------
__device__ __forceinline__ void group_wait(int bt, unsigned target) {
    __threadfence();
    __syncthreads();
    if (threadIdx.x == 0) {
        atomicAdd(&g_cnt[bt], 1u);
        unsigned v;
        do {
            asm volatile("ld.global.acquire.gpu.u32 %0, [%1];"
                         : "=r"(v) : "l"(&g_cnt[bt]) : "memory");
        } while (v < target);
    }
    __syncthreads();
}

// ---------------- input projection GEMM (f32x2) -------------------------------
__global__ void __launch_bounds__(256, 2)
xz_gemm_kernel(const float* __restrict__ x, const float* __restrict__ kern) {
    __shared__ float As[8][132];
    __shared__ float Bs[8][132];

    const int tid = threadIdx.x;
    const int nb = blockIdx.x;
    const int mb = blockIdx.y;
    const int m0 = mb * 128, n0 = nb * 128;

    const int lrow = tid >> 1;
    const int lk4  = (tid & 1) * 4;
    const int m    = m0 + lrow;
    const int tt   = m >> 8;
    const int bb   = m & 255;
    const float* xrow = x + ((size_t)bb * 512 + tt) * 128;

    const int bk = tid >> 5;
    const int bn = (tid & 31) * 4;

    const int tm = (tid >> 4) * 8;
    const int tn = (tid & 15) * 8;

    ull acc2[4][8];
#pragma unroll
    for (int i = 0; i < 4; i++)
#pragma unroll
        for (int j = 0; j < 8; j++) acc2[i][j] = 0ull;

    for (int k0 = 0; k0 < 128; k0 += 8) {
        float4 av = *(const float4*)(xrow + k0 + lk4);
        float4 bv = *(const float4*)(kern + (size_t)(k0 + bk) * 1024 + n0 + bn);
        __syncthreads();
        As[lk4 + 0][lrow] = av.x;
        As[lk4 + 1][lrow] = av.y;
        As[lk4 + 2][lrow] = av.z;
        As[lk4 + 3][lrow] = av.w;
        *(float4*)&Bs[bk][bn] = bv;
        __syncthreads();
#pragma unroll
        for (int kk = 0; kk < 8; kk++) {
            ulonglong2 a0 = *(const ulonglong2*)&As[kk][tm];
            ulonglong2 a1 = *(const ulonglong2*)&As[kk][tm + 4];
            ull ap[4] = {a0.x, a0.y, a1.x, a1.y};
            float4 b0 = *(const float4*)&Bs[kk][tn];
            float4 b1 = *(const float4*)&Bs[kk][tn + 4];
            {
                ull bd0 = dup2(b0.x), bd1 = dup2(b0.y), bd2 = dup2(b0.z), bd3 = dup2(b0.w);
#pragma unroll
                for (int i = 0; i < 4; i++) {
                    acc2[i][0] = fma2(ap[i], bd0, acc2[i][0]);
                    acc2[i][1] = fma2(ap[i], bd1, acc2[i][1]);
                    acc2[i][2] = fma2(ap[i], bd2, acc2[i][2]);
                    acc2[i][3] = fma2(ap[i], bd3, acc2[i][3]);
                }
            }
            {
                ull bd4 = dup2(b1.x), bd5 = dup2(b1.y), bd6 = dup2(b1.z), bd7 = dup2(b1.w);
#pragma unroll
                for (int i = 0; i < 4; i++) {
                    acc2[i][4] = fma2(ap[i], bd4, acc2[i][4]);
                    acc2[i][5] = fma2(ap[i], bd5, acc2[i][5]);
                    acc2[i][6] = fma2(ap[i], bd6, acc2[i][6]);
                    acc2[i][7] = fma2(ap[i], bd7, acc2[i][7]);
                }
            }
        }
    }

#pragma unroll
    for (int i2 = 0; i2 < 4; i2++) {
        float* d0 = g_xz + (size_t)(m0 + tm + 2 * i2) * 1024 + n0 + tn;
        float* d1 = d0 + 1024;
        *(float4*)(d0 + 0) = make_float4(lo32(acc2[i2][0]), lo32(acc2[i2][1]),
                                         lo32(acc2[i2][2]), lo32(acc2[i2][3]));
        *(float4*)(d0 + 4) = make_float4(lo32(acc2[i2][4]), lo32(acc2[i2][5]),
                                         lo32(acc2[i2][6]), lo32(acc2[i2][7]));
        *(float4*)(d1 + 0) = make_float4(hi32(acc2[i2][0]), hi32(acc2[i2][1]),
                                         hi32(acc2[i2][2]), hi32(acc2[i2][3]));
        *(float4*)(d1 + 4) = make_float4(hi32(acc2[i2][4]), hi32(acc2[i2][5]),
                                         hi32(acc2[i2][6]), hi32(acc2[i2][7]));
    }
}

// ---------------- fast activations -------------------------------------------
__device__ __forceinline__ float sigf(float x)     { return 1.f / (1.f + __expf(-x)); }
__device__ __forceinline__ float tanhfast(float x) { return 2.f / (1.f + __expf(-2.f * x)) - 1.f; }

// ---------------- persistent LSTM kernel -------------------------------------
// blockIdx = bt*16 + jt. Block: 32 batches x 64 local cols.
// Warp w: khalf = w&1 (k in [khalf*128, +128)), bq = w>>1 (batches bq*8..+8).
// Lane: cols {lane, lane+32}. Partials meet in zsA/zsB, summed at gate time.
__global__ void __launch_bounds__(256, 1)
lstm_kernel(const float* __restrict__ rkernel) {
    extern __shared__ float smem[];
    float* w_s = smem;                  // [64][SW]
    float* h_s = w_s + 64 * SW;         // [32][SW]
    float* zsA = h_s + 32 * SW;         // [64][33]  khalf=0 partials
    float* zsB = zsA + 64 * 33;         // [64][33]  khalf=1 partials + xz
    float* c_s = zsB + 64 * 33;         // [512]

    const int tid = threadIdx.x;
    const int bt = blockIdx.x >> 4;
    const int jt = blockIdx.x & 15;
    const int bbase = bt * 32, jbase = jt * 16;

    for (int p = tid; p < 512; p += 256) {
        int bb = p >> 4, jj = p & 15;
        c_s[p] = 0.f;
        g_h[0][bbase + bb][jbase + jj] = 0.f;
    }
    for (int idx = tid; idx < 64 * 256; idx += 256) {
        int c = idx & 63, k = idx >> 6;
        int col = (c >> 4) * 256 + jbase + (c & 15);
        w_s[c * SW + k] = rkernel[k * 1024 + col];
    }
    group_wait(bt, 16u);

    const int wid = tid >> 5, lane = tid & 31;
    const int khalf = wid & 1;
    const int b0 = (wid >> 1) * 8;
    const int c0 = lane, c1 = lane + 32;
    const int kbase = khalf * 128;
    const float* wp0 = &w_s[c0 * SW + kbase];
    const float* wp1 = &w_s[c1 * SW + kbase];

    // global columns for xz (khalf=1 warps only)
    const int colg0 = (c0 >> 4) * 256 + jbase + (c0 & 15);
    const int colg1 = (c1 >> 4) * 256 + jbase + (c1 & 15);

    // preload xz for t=0
    float xzc[16];
    if (khalf) {
#pragma unroll
        for (int r = 0; r < 8; r++) {
            const float* row = &g_xz[((size_t)(bbase + b0 + r)) * 1024];
            xzc[r * 2 + 0] = __ldcg(row + colg0);
            xzc[r * 2 + 1] = __ldcg(row + colg1);
        }
    }

    for (int t = 0; t < 512; t++) {
        const int par = t & 1;
        // h tile from L2 (cross-SM producer -> bypass L1)
        const float4* hsrc = (const float4*)&g_h[par][bbase][0];
        float4 hbuf[8];
#pragma unroll
        for (int u = 0; u < 8; u++) hbuf[u] = __ldcg(hsrc + tid + u * 256);
#pragma unroll
        for (int u = 0; u < 8; u++) {
            int i = tid + u * 256;
            *(float4*)&h_s[(i >> 6) * SW + (i & 63) * 4] = hbuf[u];
        }
        __syncthreads();

        ull acc2[8][2];
#pragma unroll
        for (int r = 0; r < 8; r++) { acc2[r][0] = 0ull; acc2[r][1] = 0ull; }
#pragma unroll 2
        for (int kk = 0; kk < 32; kk++) {
            ulonglong2 wv0 = *(const ulonglong2*)(wp0 + kk * 4);
            ulonglong2 wv1 = *(const ulonglong2*)(wp1 + kk * 4);
#pragma unroll
            for (int r = 0; r < 8; r++) {
                ulonglong2 hv = *(const ulonglong2*)&h_s[(b0 + r) * SW + kbase + kk * 4];
                acc2[r][0] = fma2(hv.x, wv0.x, acc2[r][0]);
                acc2[r][0] = fma2(hv.y, wv0.y, acc2[r][0]);
                acc2[r][1] = fma2(hv.x, wv1.x, acc2[r][1]);
                acc2[r][1] = fma2(hv.y, wv1.y, acc2[r][1]);
            }
        }

        if (khalf == 0) {
#pragma unroll
            for (int r = 0; r < 8; r++) {
                zsA[c0 * 33 + b0 + r] = lo32(acc2[r][0]) + hi32(acc2[r][0]);
                zsA[c1 * 33 + b0 + r] = lo32(acc2[r][1]) + hi32(acc2[r][1]);
            }
        } else {
#pragma unroll
            for (int r = 0; r < 8; r++) {
                zsB[c0 * 33 + b0 + r] = lo32(acc2[r][0]) + hi32(acc2[r][0]) + xzc[r * 2 + 0];
                zsB[c1 * 33 + b0 + r] = lo32(acc2[r][1]) + hi32(acc2[r][1]) + xzc[r * 2 + 1];
            }
            // prefetch xz for t+1 (off critical path)
            if (t < 511) {
#pragma unroll
                for (int r = 0; r < 8; r++) {
                    const float* row = &g_xz[((size_t)((t + 1) * 256 + bbase + b0 + r)) * 1024];
                    xzc[r * 2 + 0] = __ldcg(row + colg0);
                    xzc[r * 2 + 1] = __ldcg(row + colg1);
                }
            }
        }
        __syncthreads();

        // gates: 512 (b,j) pairs, 2 per thread
#pragma unroll
        for (int pp = 0; pp < 2; pp++) {
            int p = tid + pp * 256;
            int bb = p >> 4, jj = p & 15;
            float zi = zsA[jj * 33 + bb]        + zsB[jj * 33 + bb];
            float zf = zsA[(16 + jj) * 33 + bb] + zsB[(16 + jj) * 33 + bb];
            float zg = zsA[(32 + jj) * 33 + bb] + zsB[(32 + jj) * 33 + bb];
            float zo = zsA[(48 + jj) * 33 + bb] + zsB[(48 + jj) * 33 + bb];
            float cn = sigf(zf) * c_s[p] + sigf(zi) * tanhfast(zg);
            c_s[p] = cn;
            g_h[par ^ 1][bbase + bb][jbase + jj] = sigf(zo) * tanhfast(cn);
        }
        if (t < 511) group_wait(bt, 16u * (unsigned)(t + 2));
    }
}

// ---------------- MLP head ---------------------------------------------------
__global__ void __launch_bounds__(256)
head_kernel(const float* __restrict__ w1, const float* __restrict__ b1,
            const float* __restrict__ w2, const float* __restrict__ b2,
            float* __restrict__ out) {
    __shared__ float hs[256];
    __shared__ float ys[100];
    const int b = blockIdx.x, tid = threadIdx.x;
    hs[tid] = g_h[0][b][tid];
    __syncthreads();
    if (tid < 100) {
        float a = b1[tid];
#pragma unroll 4
        for (int k = 0; k < 256; k++) a = fmaf(hs[k], w1[k * 100 + tid], a);
        ys[tid] = fmaxf(a, 0.f);
    }
    __syncthreads();
    if (tid == 0) {
        float s = b2[0];
        for (int j = 0; j < 100; j++) s = fmaf(ys[j], w2[j], s);
        out[b] = s;
    }
}

// ---------------- launch ------------------------------------------------------
extern "C" void kernel_launch(void* const* d_in, const int* in_sizes, int n_in,
                              void* d_out, int out_size) {
    const float* x    = (const float*)d_in[0];
    const float* kern = (const float*)d_in[1];
    const float* rk   = (const float*)d_in[2];
    const float* w1   = (const float*)d_in[3];
    const float* b1   = (const float*)d_in[4];
    const float* w2   = (const float*)d_in[5];
    const float* b2   = (const float*)d_in[6];
    float* out = (float*)d_out;

    const int smem_bytes = (64 * SW + 32 * SW + 2 * 64 * 33 + 512) * 4;  // ~119KB
    cudaFuncSetAttribute(lstm_kernel, cudaFuncAttributeMaxDynamicSharedMemorySize,
                         smem_bytes);

    reset_kernel<<<1, 8>>>();
    dim3 gg(8, 1024);
    xz_gemm_kernel<<<gg, 256>>>(x, kern);
    lstm_kernel<<<LSTM_GRID, 256, smem_bytes>>>(rk);
    head_kernel<<<256, 256>>>(w1, b1, w2, b2, out);
    noop_kernel<<<1, 1>>>();   // shifts ncu's fixed capture index within the cycle
}